// round 16
// baseline (speedup 1.0000x reference)
#include <cuda_runtime.h>
#include <cuda_fp16.h>
#include <math.h>
#include <stdint.h>

#define Bb 16
#define Ss 4096
#define Dd 64
#define Hh 8
#define NB 64          // buckets per hash
#define NCHUNK 512     // Hh * NB
#define NEGV (-50000.0f)

typedef unsigned long long ull;
typedef unsigned int uint;

// ---------------- f32x2 packed-math helpers (sm_103a) -----------------------
__device__ __forceinline__ ull ffma2(ull a, ull b, ull c) {
    ull d;
    asm("fma.rn.f32x2 %0, %1, %2, %3;" : "=l"(d) : "l"(a), "l"(b), "l"(c));
    return d;
}
__device__ __forceinline__ ull pack2(float lo, float hi) {
    ull r;
    asm("mov.b64 %0, {%1, %2};" : "=l"(r) : "f"(lo), "f"(hi));
    return r;
}
__device__ __forceinline__ void unpack2(ull v, float& lo, float& hi) {
    asm("mov.b64 {%0, %1}, %2;" : "=f"(lo), "=f"(hi) : "l"(v));
}
__device__ __forceinline__ ull ld64s(const float* p) {
    return *(const ull*)p;
}
__device__ __forceinline__ uint lo32(ull v) { return (uint)v; }
__device__ __forceinline__ uint hi32(ull v) { return (uint)(v >> 32); }
__device__ __forceinline__ ull mk64(uint lo, uint hi) {
    return (ull)lo | ((ull)hi << 32);
}

// ---------------- mma helpers -------------------------------------------------
__device__ __forceinline__ void mma_f16(float* c,
    uint a0, uint a1, uint a2, uint a3, uint b0, uint b1)
{
    asm("mma.sync.aligned.m16n8k16.row.col.f32.f16.f16.f32 "
        "{%0,%1,%2,%3}, {%4,%5,%6,%7}, {%8,%9}, {%0,%1,%2,%3};"
        : "+f"(c[0]), "+f"(c[1]), "+f"(c[2]), "+f"(c[3])
        : "r"(a0), "r"(a1), "r"(a2), "r"(a3), "r"(b0), "r"(b1));
}
// pack two f32 -> f16x2 word: lower half = 'lo' (even k), upper half = 'hi'
__device__ __forceinline__ uint pack_f16x2(float lo, float hi) {
    __half2 h = __floats2half2_rn(lo, hi);
    return *(uint*)&h;
}

// old word index w (0..63) -> interleaved pair position
__device__ __forceinline__ int pairpos(int w) {
    int k0 = w >> 3, c = w & 7;
    return 8*k0 + ((c < 4) ? 2*c : 2*(c-4) + 1);
}

// ---------------- device scratch ---------------------------------------------
__device__ int   g_bucket[Bb*Hh*Ss];
__device__ int   g_perm  [Bb*Hh*Ss];
__device__ uint  g_o16 [(size_t)Bb*Hh*Ss*(Dd/2)];   // per-hash outputs, fp16x2
__device__ float g_logits[Bb*Hh*Ss];
__device__ uint  g_kn16[(size_t)Bb*Ss*(Dd/2)];      // normalized K-hat, fp16x2
__device__ uint  g_v16 [(size_t)Bb*Ss*(Dd/2)];      // V, fp16x2
__device__ float g_qs  [Bb*Ss];                     // (||q||+eps)*0.125

// ---------------- 0) per-token prep: normalize + fp16 conversion (once) ------
__global__ void __launch_bounds__(256) prep_kernel(
    const float* __restrict__ qk, const float* __restrict__ v)
{
    int tid = threadIdx.x;
    int q4  = tid & 15;
    size_t row = (size_t)blockIdx.x*16 + (tid >> 4);
    int c0 = q4*4;

    float4 xq = *(const float4*)(qk + row*Dd + c0);
    float4 xv = *(const float4*)(v  + row*Dd + c0);

    float ss = xq.x*xq.x + xq.y*xq.y + xq.z*xq.z + xq.w*xq.w;
    #pragma unroll
    for (int s = 1; s < 16; s <<= 1)
        ss += __shfl_xor_sync(0xffffffffu, ss, s, 16);
    float n = sqrtf(ss) + 1e-6f;
    float i = 1.0f / n;

    uint* kn = g_kn16 + row*(Dd/2) + q4*2;
    kn[0] = pack_f16x2(xq.x*i, xq.y*i);
    kn[1] = pack_f16x2(xq.z*i, xq.w*i);
    uint* vo = g_v16 + row*(Dd/2) + q4*2;
    vo[0] = pack_f16x2(xv.x, xv.y);
    vo[1] = pack_f16x2(xv.z, xv.w);
    if (q4 == 0) g_qs[row] = n * 0.125f;
}

// ---------------- 1) LSH hashing (bit-exact f-sequential accumulation) -------
#define TT 32
#define QT_STRIDE 34
__global__ void __launch_bounds__(256) hash_kernel(
    const float* __restrict__ qk, const float* __restrict__ rot,
    float* __restrict__ outb)
{
    __shared__ float qsT[64*QT_STRIDE];

    int blocksPerB = Ss / TT;                 // 128
    int b  = blockIdx.x / blocksPerB;
    int t0 = (blockIdx.x % blocksPerB) * TT;
    int tid = threadIdx.x;

    {
        int f = tid & 63;
        int i0 = tid >> 6;
        #pragma unroll
        for (int i = i0; i < TT; i += 4)
            qsT[f*QT_STRIDE + i] = qk[((size_t)b*Ss + t0 + i)*Dd + f];
    }
    __syncthreads();

    const float* rb = rot + (size_t)b*64*256 + tid;

    ull acc2[TT/2];
    #pragma unroll
    for (int ip = 0; ip < TT/2; ip++) acc2[ip] = 0ull;
    #pragma unroll 4
    for (int f = 0; f < 64; f++) {
        float rv = __ldg(rb + f*256);
        ull rv2 = pack2(rv, rv);
        #pragma unroll
        for (int ip = 0; ip < TT/2; ip++)
            acc2[ip] = ffma2(ld64s(qsT + f*QT_STRIDE + 2*ip), rv2, acc2[ip]);
    }

    int lane = tid & 31;
    int h    = tid >> 5;
    #pragma unroll
    for (int ip = 0; ip < TT/2; ip++) {
        float va[2];
        unpack2(acc2[ip], va[0], va[1]);
        #pragma unroll
        for (int s = 0; s < 2; s++) {
            float v = va[s];
            float val; int idx;
            if (v >= -v) { val = v;  idx = lane; }
            else         { val = -v; idx = lane + 32; }
            #pragma unroll
            for (int m = 16; m > 0; m >>= 1) {
                float ov = __shfl_xor_sync(0xffffffffu, val, m);
                int   oi = __shfl_xor_sync(0xffffffffu, idx, m);
                if (ov > val || (ov == val && oi < idx)) { val = ov; idx = oi; }
            }
            if (lane == 0) {
                int pos = ((size_t)b*Hh + h)*Ss + t0 + 2*ip + s;
                g_bucket[pos] = idx;
                if (outb) outb[pos] = (float)(idx + h*NB);
            }
        }
    }
}

// ---------------- 2) stable counting sort per (b,h), ballot-ranked ----------
__global__ void __launch_bounds__(256) sort_kernel()
{
    __shared__ int sb[Ss];
    __shared__ int cnt[NB];
    __shared__ int offs[NB + 1];
    int bh   = blockIdx.x;
    int tid  = threadIdx.x;
    int lane = tid & 31;
    int w    = tid >> 5;
    const int base = bh * Ss;

    if (tid < NB) cnt[tid] = 0;
    __syncthreads();
    for (int i = tid; i < Ss; i += 256) {
        int v = g_bucket[base + i];
        sb[i] = v;
        atomicAdd(&cnt[v], 1);
    }
    __syncthreads();
    if (tid == 0) {
        offs[0] = 0;
        for (int k = 0; k < NB; k++) offs[k+1] = offs[k] + cnt[k];
    }
    __syncthreads();

    int off[8];
    #pragma unroll
    for (int k = 0; k < 8; k++) off[k] = offs[8*w + k];

    for (int step = 0; step < Ss/32; step++) {
        int t   = step*32 + lane;
        int rel = sb[t] - 8*w;
        #pragma unroll
        for (int k = 0; k < 8; k++) {
            unsigned mask = __ballot_sync(0xffffffffu, rel == k);
            if (rel == k) {
                int pos = off[k] + __popc(mask & ((1u << lane) - 1u));
                g_perm[base + pos] = t;
            }
            off[k] += __popc(mask);
        }
    }
}

// ---------------- 3) chunked attention: fp16 QK/PV with LDS.64 layouts ------
// ks16[128][40w] : normalized K fp16x2, pair-interleaved (rows 0..63 = Q)
// probs[64][72w] : fp16x2 probs, pair-interleaved (overlays ks16 after QK)
// vhw[64][72w]   : V fp16 transposed [col][k-pair], pair-XOR swizzled
#define KS16_LD 40
#define PH_LD 72
#define V_LD 72
#define SM_KS16 0
#define SM_PH   0                       // overlay (128*40=5120 >= 64*72=4608)
#define SM_VH   (128*KS16_LD)           // 5120
#define SM_PM   (SM_VH + 64*V_LD)       // 9728
#define SM_PS   (SM_PM + 128)
#define SM_QSC  (SM_PS + 128)
#define SM_TK   (SM_QSC + 64)
#define ATTN_SMEM ((SM_TK + 128) * 4)   // 40704 bytes
__global__ void __launch_bounds__(256, 4) attn_kernel()
{
    extern __shared__ float sm[];
    uint*  ks16 = (uint*)(sm + SM_KS16);
    uint*  ph2  = (uint*)(sm + SM_PH);
    uint*  vhw  = (uint*)(sm + SM_VH);
    float* pm   = sm + SM_PM;
    float* ps   = sm + SM_PS;
    float* qsc  = sm + SM_QSC;
    int*   tk   = (int*)(sm + SM_TK);

    int b = blockIdx.x >> 9;
    int c = blockIdx.x & (NCHUNK - 1);
    int h = c >> 6;
    int cprev = (c + NCHUNK - 1) & (NCHUNK - 1);
    int tid = threadIdx.x;
    const int pbase = b * (Hh * Ss);
    const size_t tokbase = (size_t)b*Ss;

    if (tid < 64)        tk[tid] = g_perm[pbase + c*64 + tid];
    else if (tid < 128)  tk[tid] = g_perm[pbase + cprev*64 + (tid - 64)];
    __syncthreads();

    // ---- gather: pure LDG -> (PRMT) -> STS into interleaved layouts ----
    {
        int q4 = tid & 15;
        int rp = tid >> 4;
        int kw = q4*2;
        int posK0 = pairpos(2*q4);       // ks16 positions for words 2q4, 2q4+1
        int posK1 = pairpos(2*q4 + 1);
        int sxv = q4 & 7;                // vhw pair swizzle for e = 4q4+cc
        if (tid < 64) qsc[tid] = g_qs[tokbase + tk[tid]];
        #pragma unroll
        for (int pp = 0; pp < 4; pp++) {
            int r0 = 32*pp + 2*rp, r1 = r0 + 1;
            size_t t0 = tokbase + tk[r0], t1 = tokbase + tk[r1];
            uint2 kn0 = *(const uint2*)(g_kn16 + t0*(Dd/2) + kw);
            uint2 kn1 = *(const uint2*)(g_kn16 + t1*(Dd/2) + kw);
            uint2 v0  = *(const uint2*)(g_v16  + t0*(Dd/2) + kw);
            uint2 v1  = *(const uint2*)(g_v16  + t1*(Dd/2) + kw);
            ks16[r0*KS16_LD + posK0] = kn0.x;
            ks16[r0*KS16_LD + posK1] = kn0.y;
            ks16[r1*KS16_LD + posK0] = kn1.x;
            ks16[r1*KS16_LD + posK1] = kn1.y;
            // V transpose repack into swizzled pair layout
            int kp = r0 >> 1;                 // k-pair index 0..63
            int pi = ((kp >> 3) << 2) | (kp & 3);
            int bit = (kp >> 2) & 1;
            int vo = 2*(pi ^ sxv) + bit;
            int e0 = q4*4;
            vhw[(e0+0)*V_LD + vo] = __byte_perm(v0.x, v1.x, 0x5410);
            vhw[(e0+1)*V_LD + vo] = __byte_perm(v0.x, v1.x, 0x7632);
            vhw[(e0+2)*V_LD + vo] = __byte_perm(v0.y, v1.y, 0x5410);
            vhw[(e0+3)*V_LD + vo] = __byte_perm(v0.y, v1.y, 0x7632);
        }
    }
    __syncthreads();

    // ---- QK^T : 64x128x64 fp16 m16n8k16, per warp m16 x n64 ----
    int wid   = tid >> 5;
    int lane  = tid & 31;
    int gr    = lane >> 2;
    int cl    = lane & 3;
    int mrow  = 16*(wid & 3);
    int chalf = wid >> 2;
    int ncol  = 64*chalf;

    float acc[8][4];
    #pragma unroll
    for (int n = 0; n < 8; n++)
        #pragma unroll
        for (int i = 0; i < 4; i++) acc[n][i] = 0.f;

    {
        const uint* ar0 = ks16 + (mrow + gr)*KS16_LD + 2*cl;
        const uint* ar1 = ar0 + 8*KS16_LD;
        const uint* bbase = ks16 + (ncol + gr)*KS16_LD + 2*cl;
        #pragma unroll
        for (int k0 = 0; k0 < 4; k0++) {
            int o = 8*k0;
            ull a02 = *(const ull*)(ar0 + o);
            ull a13 = *(const ull*)(ar1 + o);
            uint a0 = lo32(a02), a1 = lo32(a13), a2 = hi32(a02), a3 = hi32(a13);
            #pragma unroll
            for (int n = 0; n < 8; n++) {
                ull b01 = *(const ull*)(bbase + n*8*KS16_LD + o);
                mma_f16(acc[n], a0, a1, a2, a3, lo32(b01), hi32(b01));
            }
        }
    }

    // ---- mask + scale + per-half softmax partials ----
    int row0 = mrow + gr, row1 = row0 + 8;
    int tr0 = tk[row0], tr1 = tk[row1];
    float sc0 = qsc[row0], sc1 = qsc[row1];
    float m0 = -1e30f, m1 = -1e30f;
    #pragma unroll
    for (int n = 0; n < 8; n++) {
        int j0 = ncol + 8*n + 2*cl;
        int tj0 = tk[j0], tj1 = tk[j0 + 1];
        float d0 = (tj0 == tr0) ? NEGV : acc[n][0]*sc0;
        float d1 = (tj1 == tr0) ? NEGV : acc[n][1]*sc0;
        float d2 = (tj0 == tr1) ? NEGV : acc[n][2]*sc1;
        float d3 = (tj1 == tr1) ? NEGV : acc[n][3]*sc1;
        acc[n][0] = d0; acc[n][1] = d1; acc[n][2] = d2; acc[n][3] = d3;
        m0 = fmaxf(m0, fmaxf(d0, d1));
        m1 = fmaxf(m1, fmaxf(d2, d3));
    }
    #pragma unroll
    for (int s = 1; s < 4; s <<= 1) {
        m0 = fmaxf(m0, __shfl_xor_sync(0xffffffffu, m0, s));
        m1 = fmaxf(m1, __shfl_xor_sync(0xffffffffu, m1, s));
    }
    float s0 = 0.f, s1 = 0.f;
    #pragma unroll
    for (int n = 0; n < 8; n++) {
        float e0 = __expf(acc[n][0] - m0);
        float e1 = __expf(acc[n][1] - m0);
        float e2 = __expf(acc[n][2] - m1);
        float e3 = __expf(acc[n][3] - m1);
        acc[n][0] = e0; acc[n][1] = e1; acc[n][2] = e2; acc[n][3] = e3;
        s0 += e0 + e1;
        s1 += e2 + e3;
    }
    #pragma unroll
    for (int s = 1; s < 4; s <<= 1) {
        s0 += __shfl_xor_sync(0xffffffffu, s0, s);
        s1 += __shfl_xor_sync(0xffffffffu, s1, s);
    }
    if (cl == 0) {
        pm[chalf*64 + row0] = m0;  ps[chalf*64 + row0] = s0;
        pm[chalf*64 + row1] = m1;  ps[chalf*64 + row1] = s1;
    }
    __syncthreads();   // partials visible; ALL warps done reading ks16

    float Ma0 = pm[row0], Mb0 = pm[64 + row0];
    float M0  = fmaxf(Ma0, Mb0);
    float S0  = ps[row0]*__expf(Ma0 - M0) + ps[64 + row0]*__expf(Mb0 - M0);
    float lse0 = M0 + __logf(S0);
    float Ma1 = pm[row1], Mb1 = pm[64 + row1];
    float M1  = fmaxf(Ma1, Mb1);
    float S1  = ps[row1]*__expf(Ma1 - M1) + ps[64 + row1]*__expf(Mb1 - M1);
    float lse1 = M1 + __logf(S1);

    if (cl == 0 && chalf == 0) {
        g_logits[pbase + h*Ss + tr0] = lse0;
        g_logits[pbase + h*Ss + tr1] = lse1;
    }

    // probs = e * exp(m - lse), written as pair-interleaved STS.64
    {
        float f0 = __expf(m0 - lse0);
        float f1 = __expf(m1 - lse1);
        #pragma unroll
        for (int np = 0; np < 4; np++) {
            int k0 = 4*chalf + np;
            int o = 8*k0 + 2*cl;
            int n = 2*np;
            uint w0lo = pack_f16x2(acc[n][0]*f0,   acc[n][1]*f0);
            uint w0hi = pack_f16x2(acc[n+1][0]*f0, acc[n+1][1]*f0);
            uint w1lo = pack_f16x2(acc[n][2]*f1,   acc[n][3]*f1);
            uint w1hi = pack_f16x2(acc[n+1][2]*f1, acc[n+1][3]*f1);
            *(ull*)(ph2 + row0*PH_LD + o) = mk64(w0lo, w0hi);
            *(ull*)(ph2 + row1*PH_LD + o) = mk64(w1lo, w1hi);
        }
    }
    __syncthreads();

    // ---- PV : 64x64x128 fp16, m16n8k16, per warp m16 x n32, LDS.64 frags ----
    int ocol = 32*chalf;
    float oacc[4][4];
    #pragma unroll
    for (int n = 0; n < 4; n++)
        #pragma unroll
        for (int i = 0; i < 4; i++) oacc[n][i] = 0.f;

    const uint* vb0[4];
    #pragma unroll
    for (int n = 0; n < 4; n++) {
        int e = ocol + 8*n + gr;
        int sx = (e >> 2) & 7;
        vb0[n] = vhw + e*V_LD;
        // per-k0 offset computed inside: 2*((4*k0+cl)^sx)
        // precompute xor base: (cl ^ (sx&3)) and k0-part (k0 ^ (sx>>2))
        // fold into a base pointer + per-k0 stride pattern:
        vb0[n] += 2*(( (0) + (cl ^ (sx & 3)) ) + (((sx >> 2) ^ 0) << 2));
        // store sx high bits for k0 XOR via array below
    }
    int sxh[4];
    #pragma unroll
    for (int n = 0; n < 4; n++) {
        int e = ocol + 8*n + gr;
        sxh[n] = ((e >> 2) & 7) >> 2;   // 0 or 1: XOR on k0 bit0
    }
    // NOTE: 2*((4k0+cl)^sx) = 2*(4*(k0^(sx>>2)) + (cl^(sx&3)))
    //     = 8*(k0 ^ sxh) + 2*(cl ^ sxl); vb0[n] already includes 2*(cl^sxl)
    //     and the (k0=0 ^ sxh) term; adjust per k0 with (k0 ^ sxh)*8 - (0 ^ sxh)*8.
    #pragma unroll
    for (int n = 0; n < 4; n++) vb0[n] -= 8*sxh[n];  // remove k0=0 folded term

    const uint* pr0 = ph2 + row0*PH_LD + 2*cl;
    const uint* pr1 = ph2 + row1*PH_LD + 2*cl;

    #pragma unroll 2
    for (int k0 = 0; k0 < 8; k0++) {
        int o = 8*k0;
        ull a02 = *(const ull*)(pr0 + o);
        ull a13 = *(const ull*)(pr1 + o);
        uint ah0 = lo32(a02), ah1 = lo32(a13), ah2 = hi32(a02), ah3 = hi32(a13);
        #pragma unroll
        for (int n = 0; n < 4; n++) {
            ull b01 = *(const ull*)(vb0[n] + 8*(k0 ^ sxh[n]));
            mma_f16(oacc[n], ah0, ah1, ah2, ah3, lo32(b01), hi32(b01));
        }
    }

    // ---- scatter to g_o16 (fp16x2) ----
    {
        uint* orow0 = g_o16 + (size_t)(pbase + h*Ss + tr0)*(Dd/2);
        uint* orow1 = g_o16 + (size_t)(pbase + h*Ss + tr1)*(Dd/2);
        #pragma unroll
        for (int n = 0; n < 4; n++) {
            int wcol = (ocol >> 1) + 4*n + cl;
            orow0[wcol] = pack_f16x2(oacc[n][0], oacc[n][1]);
            orow1[wcol] = pack_f16x2(oacc[n][2], oacc[n][3]);
        }
    }
}

// ---------------- 4) combine hash rounds via softmax(logits) ----------------
__global__ void __launch_bounds__(256) combine_kernel(float* __restrict__ out)
{
    size_t gid = (size_t)blockIdx.x*256 + threadIdx.x;
    if (gid >= (size_t)Bb*Ss*Dd/8) return;
    int pair = (int)(gid & 7);
    size_t bt = gid >> 3;
    int t = (int)(bt & (Ss - 1));
    int b = (int)(bt >> 12);

    float l[Hh];
    float m = -1e30f;
    #pragma unroll
    for (int h = 0; h < Hh; h++) {
        l[h] = g_logits[((size_t)(b*Hh + h))*Ss + t];
        m = fmaxf(m, l[h]);
    }
    float ssum = 0.f;
    #pragma unroll
    for (int h = 0; h < Hh; h++) { l[h] = __expf(l[h] - m); ssum += l[h]; }
    float inv = 1.f / ssum;

    float4 acc0 = make_float4(0.f, 0.f, 0.f, 0.f);
    float4 acc1 = make_float4(0.f, 0.f, 0.f, 0.f);
    #pragma unroll
    for (int h = 0; h < Hh; h++) {
        float w = l[h]*inv;
        const uint4 ow = *(const uint4*)(g_o16 + (((size_t)(b*Hh + h))*Ss + t)*(Dd/2) + pair*4);
        float2 f0 = __half22float2(*(const __half2*)&ow.x);
        float2 f1 = __half22float2(*(const __half2*)&ow.y);
        float2 f2 = __half22float2(*(const __half2*)&ow.z);
        float2 f3 = __half22float2(*(const __half2*)&ow.w);
        acc0.x += w*f0.x; acc0.y += w*f0.y; acc0.z += w*f1.x; acc0.w += w*f1.y;
        acc1.x += w*f2.x; acc1.y += w*f2.y; acc1.z += w*f3.x; acc1.w += w*f3.y;
    }
    float* dst = out + bt*Dd + pair*8;
    *(float4*)(dst)     = acc0;
    *(float4*)(dst + 4) = acc1;
}

// ---------------- launch ------------------------------------------------------
extern "C" void kernel_launch(void* const* d_in, const int* in_sizes, int n_in,
                              void* d_out, int out_size)
{
    const float* qk  = (const float*)d_in[0];
    const float* v   = (const float*)d_in[1];
    const float* rot = (const float*)d_in[2];
    float* out = (float*)d_out;

    cudaFuncSetAttribute(attn_kernel, cudaFuncAttributeMaxDynamicSharedMemorySize, ATTN_SMEM);

    float* outb = (out_size >= Bb*Ss*Dd + Bb*Hh*Ss) ? (out + (size_t)Bb*Ss*Dd) : nullptr;

    prep_kernel<<<Bb*Ss/16, 256>>>(qk, v);
    hash_kernel<<<Bb*(Ss/TT), 256>>>(qk, rot, outb);
    sort_kernel<<<Bb*Hh, 256>>>();
    attn_kernel<<<Bb*NCHUNK, 256, ATTN_SMEM>>>();
    combine_kernel<<<(int)(((size_t)Bb*Ss*Dd/8 + 255)/256), 256>>>(out);
}